// round 1
// baseline (speedup 1.0000x reference)
#include <cuda_runtime.h>
#include <mma.h>
#include <cstdint>
#include <cstdio>

using namespace nvcuda;

#define DIM 128

// ---------------- scratch (static device globals; no allocation) ----------------
#define N_K_MAX 10000
#define N_E_MAX 100000

__device__ float g_ii2[N_K_MAX * DIM];
__device__ float g_neigh[N_E_MAX * DIM];   // reused for both graphs
__device__ float g_t[N_E_MAX * DIM];       // t0 then t1
__device__ float g_hiI[N_E_MAX * DIM];
__device__ float g_src[N_E_MAX * DIM];     // src_com
__device__ float g_deg[N_E_MAX];
__device__ float g_M2s[DIM * DIM], g_M2n[DIM * DIM], g_P[DIM * DIM];
__device__ float g_F1[DIM * DIM], g_F2[DIM * DIM];
__device__ float g_b2[DIM], g_bf[DIM];

// ---------------- small utility kernels ----------------
__global__ void k_zero(float* __restrict__ p, int n4) {
    int i = blockIdx.x * blockDim.x + threadIdx.x;
    if (i < n4) ((float4*)p)[i] = make_float4(0.f, 0.f, 0.f, 0.f);
}

// neigh[r][:] /= max(deg[r],1)
__global__ void k_scale(float* __restrict__ agg, const float* __restrict__ deg, int n) {
    int i = blockIdx.x * blockDim.x + threadIdx.x;  // one float4 per thread
    int total = n * (DIM / 4);
    if (i >= total) return;
    int row = i / (DIM / 4);
    float s = 1.0f / fmaxf(deg[row], 1.0f);
    float4 v = ((float4*)agg)[i];
    v.x *= s; v.y *= s; v.z *= s; v.w *= s;
    ((float4*)agg)[i] = v;
}

// ---------------- edge aggregation: one warp per edge, red.v4 into agg ----------------
__global__ void k_aggregate(const float* __restrict__ src,
                            const int* __restrict__ sidx,
                            const int* __restrict__ didx,
                            const float* __restrict__ ew,  // nullable
                            float* __restrict__ agg,
                            float* __restrict__ deg,
                            int E)
{
    int w = (blockIdx.x * blockDim.x + threadIdx.x) >> 5;
    int lane = threadIdx.x & 31;
    if (w >= E) return;
    int s = __ldg(sidx + w);
    int d = __ldg(didx + w);
    float4 v = ((const float4*)(src + (size_t)s * DIM))[lane];
    if (ew) {
        float t = __ldg(ew + w);
        v.x *= t; v.y *= t; v.z *= t; v.w *= t;
    }
    float* a = agg + (size_t)d * DIM + lane * 4;
    asm volatile("red.global.add.v4.f32 [%0], {%1,%2,%3,%4};"
                 :: "l"(a), "f"(v.x), "f"(v.y), "f"(v.z), "f"(v.w) : "memory");
    if (lane == 0) atomicAdd(deg + d, 1.0f);
}

// ---------------- weight folding (tiny 128x128 GEMMs, exact fp32) ----------------
// M2s = w2 @ ekS1 ; M2n = w2 @ ekN1 ; b2 = w2 @ ekb1 + w2b ; P = Cb @ w3
__global__ void k_combo1(const float* __restrict__ w2, const float* __restrict__ w2b,
                         const float* __restrict__ ekS, const float* __restrict__ ekN,
                         const float* __restrict__ ekb,
                         const float* __restrict__ combW, const float* __restrict__ w3,
                         float* __restrict__ M2s, float* __restrict__ M2n,
                         float* __restrict__ b2, float* __restrict__ P)
{
    int j = blockIdx.x, k = threadIdx.x;
    const float* ekS1 = ekS + DIM * DIM;
    const float* ekN1 = ekN + DIM * DIM;
    const float* ekb1 = ekb + DIM;
    float s1 = 0.f, s2 = 0.f, s3 = 0.f;
    for (int t = 0; t < DIM; t++) {
        float a = w2[j * DIM + t];
        s1 += a * ekS1[t * DIM + k];
        s2 += a * ekN1[t * DIM + k];
        float cbv = combW[j * 2 * DIM + DIM + t];
        s3 += cbv * w3[t * DIM + k];
    }
    M2s[j * DIM + k] = s1;
    M2n[j * DIM + k] = s2;
    P[j * DIM + k] = s3;
    if (k == 0) {
        float b = 0.f;
        for (int t = 0; t < DIM; t++) b += w2[j * DIM + t] * ekb1[t];
        b2[j] = b + w2b[j];
    }
}

// F1 = P @ eeS1 ; F2 = P @ eeN1 ; bf = P @ eeb1 + Cb @ w3b + comb_b
__global__ void k_combo2(const float* __restrict__ P,
                         const float* __restrict__ eeS, const float* __restrict__ eeN,
                         const float* __restrict__ eeb,
                         const float* __restrict__ combW, const float* __restrict__ w3b,
                         const float* __restrict__ combb,
                         float* __restrict__ F1, float* __restrict__ F2,
                         float* __restrict__ bf)
{
    int j = blockIdx.x, k = threadIdx.x;
    const float* eeS1 = eeS + DIM * DIM;
    const float* eeN1 = eeN + DIM * DIM;
    const float* eeb1 = eeb + DIM;
    float s1 = 0.f, s2 = 0.f;
    for (int t = 0; t < DIM; t++) {
        float p = P[j * DIM + t];
        s1 += p * eeS1[t * DIM + k];
        s2 += p * eeN1[t * DIM + k];
    }
    F1[j * DIM + k] = s1;
    F2[j * DIM + k] = s2;
    if (k == 0) {
        float b = 0.f;
        for (int t = 0; t < DIM; t++)
            b += P[j * DIM + t] * eeb1[t] + combW[j * 2 * DIM + DIM + t] * w3b[t];
        bf[j] = b + combb[j];
    }
}

// ---------------- fused multi-input GEMM: C = act(sum_i A_i @ W_i^T + bias) ----------------
// A_i: [N,128] row-major. W_i: [128, ldw_i] row-major, use a 128x128 slice (C[r,j] = sum_k A[r,k]*W[j,k]).
// Block: 128 rows x 128 cols. 8 warps in a 2x4 layout (warp tile 64x32). tf32 HMMA, fp32 accum.
template<int NIN, int ACT>  // ACT: 0 none, 1 relu, 2 leaky(0.2)
__global__ void __launch_bounds__(256) k_gemm(
    const float* __restrict__ A0, const float* __restrict__ W0, int ldw0,
    const float* __restrict__ A1, const float* __restrict__ W1, int ldw1,
    const float* __restrict__ A2, const float* __restrict__ W2, int ldw2,
    const float* __restrict__ bias, float* __restrict__ C, int N)
{
    constexpr int BK = 16;
    __shared__ __align__(16) float As[128 * BK];  // As[r][k]
    __shared__ __align__(16) float Ws[128 * BK];  // Ws[n][k]

    const int tid = threadIdx.x;
    const int warp = tid >> 5;
    const int lane = tid & 31;
    const int row0 = blockIdx.x * 128;
    const int wm = warp >> 2;   // 0..1 -> 64 rows each
    const int wn = warp & 3;    // 0..3 -> 32 cols each

    wmma::fragment<wmma::accumulator, 16, 16, 8, float> acc[4][2];
    #pragma unroll
    for (int i = 0; i < 4; i++)
        #pragma unroll
        for (int j = 0; j < 2; j++) wmma::fill_fragment(acc[i][j], 0.0f);

    const float* Aarr[3] = {A0, A1, A2};
    const float* Warr[3] = {W0, W1, W2};
    const int ldarr[3] = {ldw0, ldw1, ldw2};

    #pragma unroll
    for (int in = 0; in < NIN; in++) {
        const float* A = Aarr[in];
        const float* W = Warr[in];
        const int ldw = ldarr[in];
        for (int k0 = 0; k0 < DIM; k0 += BK) {
            __syncthreads();
            #pragma unroll
            for (int it = 0; it < 2; it++) {
                int idx = tid + it * 256;      // float4 slot 0..511
                int r = idx >> 2;              // 0..127
                int c4 = (idx & 3) * 4;
                float4 v = make_float4(0.f, 0.f, 0.f, 0.f);
                if (row0 + r < N) v = *(const float4*)(A + (size_t)(row0 + r) * DIM + k0 + c4);
                *(float4*)(As + r * BK + c4) = v;
                float4 wv = *(const float4*)(W + (size_t)r * ldw + k0 + c4);
                *(float4*)(Ws + r * BK + c4) = wv;
            }
            __syncthreads();
            #pragma unroll
            for (int kf = 0; kf < 2; kf++) {
                wmma::fragment<wmma::matrix_a, 16, 16, 8, wmma::precision::tf32, wmma::row_major> af[4];
                wmma::fragment<wmma::matrix_b, 16, 16, 8, wmma::precision::tf32, wmma::col_major> bfr[2];
                #pragma unroll
                for (int mf = 0; mf < 4; mf++) {
                    wmma::load_matrix_sync(af[mf], As + (wm * 64 + mf * 16) * BK + kf * 8, BK);
                    #pragma unroll
                    for (int e = 0; e < af[mf].num_elements; e++)
                        af[mf].x[e] = wmma::__float_to_tf32(af[mf].x[e]);
                }
                #pragma unroll
                for (int nf = 0; nf < 2; nf++) {
                    wmma::load_matrix_sync(bfr[nf], Ws + (wn * 32 + nf * 16) * BK + kf * 8, BK);
                    #pragma unroll
                    for (int e = 0; e < bfr[nf].num_elements; e++)
                        bfr[nf].x[e] = wmma::__float_to_tf32(bfr[nf].x[e]);
                }
                #pragma unroll
                for (int mf = 0; mf < 4; mf++)
                    #pragma unroll
                    for (int nf = 0; nf < 2; nf++)
                        wmma::mma_sync(acc[mf][nf], af[mf], bfr[nf], acc[mf][nf]);
            }
        }
    }

    __syncthreads();  // As/Ws reused as epilogue staging
    float* cw = (warp < 4 ? As : Ws) + (warp & 3) * 512;  // 16x32 per warp
    const float bj = bias[wn * 32 + lane];
    #pragma unroll
    for (int mf = 0; mf < 4; mf++) {
        wmma::store_matrix_sync(cw, acc[mf][0], 32, wmma::mem_row_major);
        wmma::store_matrix_sync(cw + 16, acc[mf][1], 32, wmma::mem_row_major);
        __syncwarp();
        int rbase = row0 + wm * 64 + mf * 16;
        #pragma unroll
        for (int r = 0; r < 16; r++) {
            int row = rbase + r;
            if (row < N) {
                float v = cw[r * 32 + lane] + bj;
                if (ACT == 1) v = fmaxf(v, 0.0f);
                else if (ACT == 2) v = (v >= 0.0f) ? v : 0.2f * v;
                C[(size_t)row * DIM + wn * 32 + lane] = v;
            }
        }
        __syncwarp();
    }
}

// ---------------- driver ----------------
extern "C" void kernel_launch(void* const* d_in, const int* in_sizes, int n_in,
                              void* d_out, int out_size)
{
    const float* ii    = (const float*)d_in[0];
    const float* e_emb = (const float*)d_in[1];
    const float* kemb  = (const float*)d_in[2];
    const float* cf_ew = (const float*)d_in[3];
    const int*   b_src = (const int*)d_in[4];
    const int*   b_dst = (const int*)d_in[5];
    const int*   c_src = (const int*)d_in[6];
    const int*   c_dst = (const int*)d_in[7];
    const float* ekS = (const float*)d_in[8];
    const float* ekN = (const float*)d_in[9];
    const float* ekb = (const float*)d_in[10];
    const float* eeS = (const float*)d_in[11];
    const float* eeN = (const float*)d_in[12];
    const float* eeb = (const float*)d_in[13];
    const float* w1W = (const float*)d_in[14];
    const float* w1b = (const float*)d_in[15];
    const float* w2W = (const float*)d_in[16];
    const float* w2b = (const float*)d_in[17];
    const float* w3W = (const float*)d_in[18];
    const float* w3b = (const float*)d_in[19];
    const float* w4W = (const float*)d_in[20];
    const float* w4b = (const float*)d_in[21];
    const float* cW  = (const float*)d_in[22];
    const float* cb  = (const float*)d_in[23];
    float* out = (float*)d_out;

    const int n_k = in_sizes[0] / DIM;
    const int n_e = in_sizes[1] / DIM;
    const int E   = in_sizes[3];

    float *ii2, *neigh, *t, *hiI, *srcc, *deg, *M2s, *M2n, *P, *F1, *F2, *b2, *bfv;
    cudaGetSymbolAddress((void**)&ii2,   g_ii2);
    cudaGetSymbolAddress((void**)&neigh, g_neigh);
    cudaGetSymbolAddress((void**)&t,     g_t);
    cudaGetSymbolAddress((void**)&hiI,   g_hiI);
    cudaGetSymbolAddress((void**)&srcc,  g_src);
    cudaGetSymbolAddress((void**)&deg,   g_deg);
    cudaGetSymbolAddress((void**)&M2s,   g_M2s);
    cudaGetSymbolAddress((void**)&M2n,   g_M2n);
    cudaGetSymbolAddress((void**)&P,     g_P);
    cudaGetSymbolAddress((void**)&F1,    g_F1);
    cudaGetSymbolAddress((void**)&F2,    g_F2);
    cudaGetSymbolAddress((void**)&b2,    g_b2);
    cudaGetSymbolAddress((void**)&bfv,   g_bf);

    const int gE  = (int)(((long long)E * 32 + 255) / 256);
    const int gNe = (n_e + 127) / 128;
    const int gNk = (n_k + 127) / 128;
    const int zNeigh = (n_e * (DIM / 4) + 255) / 256;
    const int zDeg   = (n_e / 4 + 255) / 256;
    const int gScale = (n_e * (DIM / 4) + 255) / 256;

    // fold small weights
    k_combo1<<<DIM, DIM>>>(w2W, w2b, ekS, ekN, ekb, cW, w3W, M2s, M2n, b2, P);
    k_combo2<<<DIM, DIM>>>(P, eeS, eeN, eeb, cW, w3b, cb, F1, F2, bfv);

    // ii2 = [ii | k_emb] @ w4^T + w4b
    k_gemm<2, 0><<<gNk, 256>>>(ii, w4W, 2 * DIM, kemb, w4W + DIM, 2 * DIM,
                               nullptr, nullptr, 0, w4b, ii2, n_k);

    // belong aggregation (mean of ii2 over edges) -- shared by both SAGE layers
    k_zero<<<zNeigh, 256>>>(neigh, n_e * (DIM / 4));
    k_zero<<<zDeg, 256>>>(deg, n_e / 4);
    k_aggregate<<<gE, 256>>>(ii2, b_src, b_dst, nullptr, neigh, deg, E);
    k_scale<<<gScale, 256>>>(neigh, deg, n_e);

    // t0 = relu(e_emb @ ekS0^T + neigh @ ekN0^T + ekb0)
    k_gemm<2, 1><<<gNe, 256>>>(e_emb, ekS, DIM, neigh, ekN, DIM,
                               nullptr, nullptr, 0, ekb, t, n_e);
    // h_iI = t0 @ (w2·ekS1)^T + neigh @ (w2·ekN1)^T + (w2·ekb1 + w2b)
    k_gemm<2, 0><<<gNe, 256>>>(t, M2s, DIM, neigh, M2n, DIM,
                               nullptr, nullptr, 0, b2, hiI, n_e);
    // src_com = [h_iI | e_emb] @ w1^T + w1b
    k_gemm<2, 0><<<gNe, 256>>>(hiI, w1W, 2 * DIM, e_emb, w1W + DIM, 2 * DIM,
                               nullptr, nullptr, 0, w1b, srcc, n_e);

    // collab aggregation (edge-weighted mean of src_com) -- shared by both layers
    k_zero<<<zNeigh, 256>>>(neigh, n_e * (DIM / 4));
    k_zero<<<zDeg, 256>>>(deg, n_e / 4);
    k_aggregate<<<gE, 256>>>(srcc, c_src, c_dst, cf_ew, neigh, deg, E);
    k_scale<<<gScale, 256>>>(neigh, deg, n_e);

    // t1 = relu(e_emb @ eeS0^T + neigh @ eeN0^T + eeb0)
    k_gemm<2, 1><<<gNe, 256>>>(e_emb, eeS, DIM, neigh, eeN, DIM,
                               nullptr, nullptr, 0, eeb, t, n_e);
    // out = leaky( h_iI @ Ca^T + t1 @ F1^T + neigh @ F2^T + bf )   [w3, Cb, comb folded]
    k_gemm<3, 2><<<gNe, 256>>>(hiI, cW, 2 * DIM, t, F1, DIM, neigh, F2, DIM,
                               bfv, out, n_e);
}

// round 2
// speedup vs baseline: 1.2152x; 1.2152x over previous
#include <cuda_runtime.h>
#include <mma.h>
#include <cstdint>

using namespace nvcuda;

#define DIM 128
#define N_K_MAX 10000
#define N_E_MAX 100000
#define E_MAX   2000000
#define SCAN_CHUNK 1024

// ---------------- scratch (static device globals; no allocation) ----------------
__device__ float g_ii2[N_K_MAX * DIM];
__device__ float g_neigh[N_E_MAX * DIM];
__device__ float g_t[N_E_MAX * DIM];
__device__ float g_hiI[N_E_MAX * DIM];
__device__ float g_src[N_E_MAX * DIM];
__device__ int   g_cnt[N_E_MAX];
__device__ int   g_rowstart[N_E_MAX];
__device__ int   g_cursor[N_E_MAX];
__device__ int   g_chunkoff[256];
__device__ int   g_esrc[E_MAX];
__device__ float g_eew[E_MAX];
__device__ float g_M2s[DIM * DIM], g_M2n[DIM * DIM], g_P[DIM * DIM];
__device__ float g_F1[DIM * DIM], g_F2[DIM * DIM];
__device__ float g_b2[DIM], g_bf[DIM];

// ---------------- CSR build ----------------
__global__ void k_zero_i(int* __restrict__ p, int n) {
    int i = blockIdx.x * blockDim.x + threadIdx.x;
    if (i < n) p[i] = 0;
}

__global__ void k_hist(const int* __restrict__ didx, int* __restrict__ cnt, int E) {
    int i = blockIdx.x * blockDim.x + threadIdx.x;
    if (i < E) atomicAdd(cnt + __ldg(didx + i), 1);
}

// per-chunk exclusive scan (chunk = 1024 elems, 256 threads x 4)
__global__ void k_scan1(const int* __restrict__ cnt, int* __restrict__ excl,
                        int* __restrict__ sums, int n) {
    __shared__ int warp_sums[8];
    int t = threadIdx.x;
    int lane = t & 31, w = t >> 5;
    int idx = blockIdx.x * SCAN_CHUNK + t * 4;
    int a0 = 0, a1 = 0, a2 = 0, a3 = 0;
    if (idx + 3 < n) {
        int4 v = *(const int4*)(cnt + idx);
        a0 = v.x; a1 = v.y; a2 = v.z; a3 = v.w;
    } else {
        if (idx + 0 < n) a0 = cnt[idx + 0];
        if (idx + 1 < n) a1 = cnt[idx + 1];
        if (idx + 2 < n) a2 = cnt[idx + 2];
        if (idx + 3 < n) a3 = cnt[idx + 3];
    }
    int s0 = a0, s1 = s0 + a1, s2 = s1 + a2, s3 = s2 + a3;  // inclusive in-thread
    int tot = s3;
    int x = tot;
    #pragma unroll
    for (int o = 1; o < 32; o <<= 1) {
        int y = __shfl_up_sync(0xffffffffu, x, o);
        if (lane >= o) x += y;
    }
    if (lane == 31) warp_sums[w] = x;
    __syncthreads();
    if (w == 0) {
        int y = (lane < 8) ? warp_sums[lane] : 0;
        #pragma unroll
        for (int o = 1; o < 8; o <<= 1) {
            int z = __shfl_up_sync(0xffffffffu, y, o);
            if (lane >= o) y += z;
        }
        if (lane < 8) warp_sums[lane] = y;
    }
    __syncthreads();
    int base = ((w > 0) ? warp_sums[w - 1] : 0) + (x - tot);  // exclusive up to this thread
    if (idx + 0 < n) excl[idx + 0] = base;
    if (idx + 1 < n) excl[idx + 1] = base + s0;
    if (idx + 2 < n) excl[idx + 2] = base + s1;
    if (idx + 3 < n) excl[idx + 3] = base + s2;
    if (t == 0) sums[blockIdx.x] = warp_sums[7];  // block total
}

__global__ void k_scan2(const int* __restrict__ sums, int* __restrict__ off, int nchunks) {
    __shared__ int sh[256];
    int t = threadIdx.x;
    sh[t] = (t < nchunks) ? sums[t] : 0;
    __syncthreads();
    for (int o = 1; o < 256; o <<= 1) {
        int v = (t >= o) ? sh[t - o] : 0;
        __syncthreads();
        sh[t] += v;
        __syncthreads();
    }
    if (t < nchunks) off[t] = (t == 0) ? 0 : sh[t - 1];  // exclusive
}

__global__ void k_scan3(int* __restrict__ excl, int* __restrict__ cursor,
                        const int* __restrict__ off, int n) {
    int i = blockIdx.x * blockDim.x + threadIdx.x;
    if (i >= n) return;
    int v = excl[i] + off[i / SCAN_CHUNK];
    excl[i] = v;
    cursor[i] = v;
}

template<bool HASEW>
__global__ void k_scatter(const int* __restrict__ sidx, const int* __restrict__ didx,
                          const float* __restrict__ ew, int* __restrict__ cursor,
                          int* __restrict__ esrc, float* __restrict__ eew, int E) {
    int i = blockIdx.x * blockDim.x + threadIdx.x;
    if (i >= E) return;
    int d = __ldg(didx + i);
    int pos = atomicAdd(cursor + d, 1);
    esrc[pos] = __ldg(sidx + i);
    if (HASEW) eew[pos] = __ldg(ew + i);
}

// gather-only aggregation: one warp per dst row, mean of neighbor rows
template<bool HASEW>
__global__ void __launch_bounds__(256) k_agg_csr(
    const float* __restrict__ src, const int* __restrict__ rowstart,
    const int* __restrict__ cnt, const int* __restrict__ esrc,
    const float* __restrict__ eew, float* __restrict__ out, int n)
{
    int row = (blockIdx.x * blockDim.x + threadIdx.x) >> 5;
    int lane = threadIdx.x & 31;
    if (row >= n) return;
    int s0 = __ldg(rowstart + row);
    int c  = __ldg(cnt + row);
    float ax = 0.f, ay = 0.f, az = 0.f, aw = 0.f;
    int e = s0, end = s0 + c;
    // unroll-by-2 with index prefetch for MLP
    for (; e + 1 < end; e += 2) {
        int sA = __ldg(esrc + e), sB = __ldg(esrc + e + 1);
        float wA = HASEW ? __ldg(eew + e)     : 1.f;
        float wB = HASEW ? __ldg(eew + e + 1) : 1.f;
        float4 vA = __ldg((const float4*)(src + (size_t)sA * DIM) + lane);
        float4 vB = __ldg((const float4*)(src + (size_t)sB * DIM) + lane);
        ax += vA.x * wA + vB.x * wB;
        ay += vA.y * wA + vB.y * wB;
        az += vA.z * wA + vB.z * wB;
        aw += vA.w * wA + vB.w * wB;
    }
    if (e < end) {
        int s = __ldg(esrc + e);
        float w = HASEW ? __ldg(eew + e) : 1.f;
        float4 v = __ldg((const float4*)(src + (size_t)s * DIM) + lane);
        ax += v.x * w; ay += v.y * w; az += v.z * w; aw += v.w * w;
    }
    float inv = 1.f / fmaxf((float)c, 1.f);
    float4 r = make_float4(ax * inv, ay * inv, az * inv, aw * inv);
    ((float4*)(out + (size_t)row * DIM))[lane] = r;
}

// ---------------- weight folding (tiny 128x128 GEMMs, exact fp32) ----------------
__global__ void k_combo1(const float* __restrict__ w2, const float* __restrict__ w2b,
                         const float* __restrict__ ekS, const float* __restrict__ ekN,
                         const float* __restrict__ ekb,
                         const float* __restrict__ combW, const float* __restrict__ w3,
                         float* __restrict__ M2s, float* __restrict__ M2n,
                         float* __restrict__ b2, float* __restrict__ P)
{
    int j = blockIdx.x, k = threadIdx.x;
    const float* ekS1 = ekS + DIM * DIM;
    const float* ekN1 = ekN + DIM * DIM;
    const float* ekb1 = ekb + DIM;
    float s1 = 0.f, s2 = 0.f, s3 = 0.f;
    for (int t = 0; t < DIM; t++) {
        float a = w2[j * DIM + t];
        s1 += a * ekS1[t * DIM + k];
        s2 += a * ekN1[t * DIM + k];
        float cbv = combW[j * 2 * DIM + DIM + t];
        s3 += cbv * w3[t * DIM + k];
    }
    M2s[j * DIM + k] = s1;
    M2n[j * DIM + k] = s2;
    P[j * DIM + k] = s3;
    if (k == 0) {
        float b = 0.f;
        for (int t = 0; t < DIM; t++) b += w2[j * DIM + t] * ekb1[t];
        b2[j] = b + w2b[j];
    }
}

__global__ void k_combo2(const float* __restrict__ P,
                         const float* __restrict__ eeS, const float* __restrict__ eeN,
                         const float* __restrict__ eeb,
                         const float* __restrict__ combW, const float* __restrict__ w3b,
                         const float* __restrict__ combb,
                         float* __restrict__ F1, float* __restrict__ F2,
                         float* __restrict__ bf)
{
    int j = blockIdx.x, k = threadIdx.x;
    const float* eeS1 = eeS + DIM * DIM;
    const float* eeN1 = eeN + DIM * DIM;
    const float* eeb1 = eeb + DIM;
    float s1 = 0.f, s2 = 0.f;
    for (int t = 0; t < DIM; t++) {
        float p = P[j * DIM + t];
        s1 += p * eeS1[t * DIM + k];
        s2 += p * eeN1[t * DIM + k];
    }
    F1[j * DIM + k] = s1;
    F2[j * DIM + k] = s2;
    if (k == 0) {
        float b = 0.f;
        for (int t = 0; t < DIM; t++)
            b += P[j * DIM + t] * eeb1[t] + combW[j * 2 * DIM + DIM + t] * w3b[t];
        bf[j] = b + combb[j];
    }
}

// ---------------- fused multi-input GEMM (tf32 wmma): C = act(sum_i A_i @ W_i^T + bias) ----------------
template<int NIN, int ACT>  // ACT: 0 none, 1 relu, 2 leaky(0.2)
__global__ void __launch_bounds__(256) k_gemm(
    const float* __restrict__ A0, const float* __restrict__ W0, int ldw0,
    const float* __restrict__ A1, const float* __restrict__ W1, int ldw1,
    const float* __restrict__ A2, const float* __restrict__ W2, int ldw2,
    const float* __restrict__ bias, float* __restrict__ C, int N)
{
    constexpr int BK = 16;
    __shared__ __align__(16) float As[128 * BK];
    __shared__ __align__(16) float Ws[128 * BK];

    const int tid = threadIdx.x;
    const int warp = tid >> 5;
    const int lane = tid & 31;
    const int row0 = blockIdx.x * 128;
    const int wm = warp >> 2;
    const int wn = warp & 3;

    wmma::fragment<wmma::accumulator, 16, 16, 8, float> acc[4][2];
    #pragma unroll
    for (int i = 0; i < 4; i++)
        #pragma unroll
        for (int j = 0; j < 2; j++) wmma::fill_fragment(acc[i][j], 0.0f);

    const float* Aarr[3] = {A0, A1, A2};
    const float* Warr[3] = {W0, W1, W2};
    const int ldarr[3] = {ldw0, ldw1, ldw2};

    #pragma unroll
    for (int in = 0; in < NIN; in++) {
        const float* A = Aarr[in];
        const float* W = Warr[in];
        const int ldw = ldarr[in];
        for (int k0 = 0; k0 < DIM; k0 += BK) {
            __syncthreads();
            #pragma unroll
            for (int it = 0; it < 2; it++) {
                int idx = tid + it * 256;
                int r = idx >> 2;
                int c4 = (idx & 3) * 4;
                float4 v = make_float4(0.f, 0.f, 0.f, 0.f);
                if (row0 + r < N) v = *(const float4*)(A + (size_t)(row0 + r) * DIM + k0 + c4);
                *(float4*)(As + r * BK + c4) = v;
                float4 wv = *(const float4*)(W + (size_t)r * ldw + k0 + c4);
                *(float4*)(Ws + r * BK + c4) = wv;
            }
            __syncthreads();
            #pragma unroll
            for (int kf = 0; kf < 2; kf++) {
                wmma::fragment<wmma::matrix_a, 16, 16, 8, wmma::precision::tf32, wmma::row_major> af[4];
                wmma::fragment<wmma::matrix_b, 16, 16, 8, wmma::precision::tf32, wmma::col_major> bfr[2];
                #pragma unroll
                for (int mf = 0; mf < 4; mf++) {
                    wmma::load_matrix_sync(af[mf], As + (wm * 64 + mf * 16) * BK + kf * 8, BK);
                    #pragma unroll
                    for (int e = 0; e < af[mf].num_elements; e++)
                        af[mf].x[e] = wmma::__float_to_tf32(af[mf].x[e]);
                }
                #pragma unroll
                for (int nf = 0; nf < 2; nf++) {
                    wmma::load_matrix_sync(bfr[nf], Ws + (wn * 32 + nf * 16) * BK + kf * 8, BK);
                    #pragma unroll
                    for (int e = 0; e < bfr[nf].num_elements; e++)
                        bfr[nf].x[e] = wmma::__float_to_tf32(bfr[nf].x[e]);
                }
                #pragma unroll
                for (int mf = 0; mf < 4; mf++)
                    #pragma unroll
                    for (int nf = 0; nf < 2; nf++)
                        wmma::mma_sync(acc[mf][nf], af[mf], bfr[nf], acc[mf][nf]);
            }
        }
    }

    __syncthreads();
    float* cw = (warp < 4 ? As : Ws) + (warp & 3) * 512;
    const float bj = bias[wn * 32 + lane];
    #pragma unroll
    for (int mf = 0; mf < 4; mf++) {
        wmma::store_matrix_sync(cw, acc[mf][0], 32, wmma::mem_row_major);
        wmma::store_matrix_sync(cw + 16, acc[mf][1], 32, wmma::mem_row_major);
        __syncwarp();
        int rbase = row0 + wm * 64 + mf * 16;
        #pragma unroll
        for (int r = 0; r < 16; r++) {
            int row = rbase + r;
            if (row < N) {
                float v = cw[r * 32 + lane] + bj;
                if (ACT == 1) v = fmaxf(v, 0.0f);
                else if (ACT == 2) v = (v >= 0.0f) ? v : 0.2f * v;
                C[(size_t)row * DIM + wn * 32 + lane] = v;
            }
        }
        __syncwarp();
    }
}

// ---------------- driver ----------------
extern "C" void kernel_launch(void* const* d_in, const int* in_sizes, int n_in,
                              void* d_out, int out_size)
{
    const float* ii    = (const float*)d_in[0];
    const float* e_emb = (const float*)d_in[1];
    const float* kemb  = (const float*)d_in[2];
    const float* cf_ew = (const float*)d_in[3];
    const int*   b_src = (const int*)d_in[4];
    const int*   b_dst = (const int*)d_in[5];
    const int*   c_src = (const int*)d_in[6];
    const int*   c_dst = (const int*)d_in[7];
    const float* ekS = (const float*)d_in[8];
    const float* ekN = (const float*)d_in[9];
    const float* ekb = (const float*)d_in[10];
    const float* eeS = (const float*)d_in[11];
    const float* eeN = (const float*)d_in[12];
    const float* eeb = (const float*)d_in[13];
    const float* w1W = (const float*)d_in[14];
    const float* w1b = (const float*)d_in[15];
    const float* w2W = (const float*)d_in[16];
    const float* w2b = (const float*)d_in[17];
    const float* w3W = (const float*)d_in[18];
    const float* w3b = (const float*)d_in[19];
    const float* w4W = (const float*)d_in[20];
    const float* w4b = (const float*)d_in[21];
    const float* cW  = (const float*)d_in[22];
    const float* cb  = (const float*)d_in[23];
    float* out = (float*)d_out;

    const int n_k = in_sizes[0] / DIM;
    const int n_e = in_sizes[1] / DIM;
    const int Eb  = in_sizes[4];
    const int Ec  = in_sizes[6];

    float *ii2, *neigh, *t, *hiI, *srcc, *M2s, *M2n, *P, *F1, *F2, *b2, *bfv, *eew;
    int *cnt, *rowstart, *cursor, *chunkoff, *esrc;
    cudaGetSymbolAddress((void**)&ii2,   g_ii2);
    cudaGetSymbolAddress((void**)&neigh, g_neigh);
    cudaGetSymbolAddress((void**)&t,     g_t);
    cudaGetSymbolAddress((void**)&hiI,   g_hiI);
    cudaGetSymbolAddress((void**)&srcc,  g_src);
    cudaGetSymbolAddress((void**)&cnt,      g_cnt);
    cudaGetSymbolAddress((void**)&rowstart, g_rowstart);
    cudaGetSymbolAddress((void**)&cursor,   g_cursor);
    cudaGetSymbolAddress((void**)&chunkoff, g_chunkoff);
    cudaGetSymbolAddress((void**)&esrc,     g_esrc);
    cudaGetSymbolAddress((void**)&eew,      g_eew);
    cudaGetSymbolAddress((void**)&M2s,   g_M2s);
    cudaGetSymbolAddress((void**)&M2n,   g_M2n);
    cudaGetSymbolAddress((void**)&P,     g_P);
    cudaGetSymbolAddress((void**)&F1,    g_F1);
    cudaGetSymbolAddress((void**)&F2,    g_F2);
    cudaGetSymbolAddress((void**)&b2,    g_b2);
    cudaGetSymbolAddress((void**)&bfv,   g_bf);

    const int gNe = (n_e + 127) / 128;
    const int gNk = (n_k + 127) / 128;
    const int gRows = (n_e * 32 + 255) / 256;       // warp-per-row agg
    const int nchunks = (n_e + SCAN_CHUNK - 1) / SCAN_CHUNK;

    // fold small weights
    k_combo1<<<DIM, DIM>>>(w2W, w2b, ekS, ekN, ekb, cW, w3W, M2s, M2n, b2, P);
    k_combo2<<<DIM, DIM>>>(P, eeS, eeN, eeb, cW, w3b, cb, F1, F2, bfv);

    // ii2 = [ii | k_emb] @ w4^T + w4b
    k_gemm<2, 0><<<gNk, 256>>>(ii, w4W, 2 * DIM, kemb, w4W + DIM, 2 * DIM,
                               nullptr, nullptr, 0, w4b, ii2, n_k);

    // ---- belong graph: CSR build + gather-mean of ii2 ----
    k_zero_i<<<(n_e + 255) / 256, 256>>>(cnt, n_e);
    k_hist<<<(Eb + 255) / 256, 256>>>(b_dst, cnt, Eb);
    k_scan1<<<nchunks, 256>>>(cnt, rowstart, chunkoff + 128, n_e);   // reuse tail of chunkoff? no:
    k_scan2<<<1, 256>>>(chunkoff + 128, chunkoff, nchunks);
    k_scan3<<<(n_e + 255) / 256, 256>>>(rowstart, cursor, chunkoff, n_e);
    k_scatter<false><<<(Eb + 255) / 256, 256>>>(b_src, b_dst, nullptr, cursor, esrc, nullptr, Eb);
    k_agg_csr<false><<<gRows, 256>>>(ii2, rowstart, cnt, esrc, nullptr, neigh, n_e);

    // t0 = relu(e_emb @ ekS0^T + neigh @ ekN0^T + ekb0)
    k_gemm<2, 1><<<gNe, 256>>>(e_emb, ekS, DIM, neigh, ekN, DIM,
                               nullptr, nullptr, 0, ekb, t, n_e);
    // h_iI = t0 @ (w2·ekS1)^T + neigh @ (w2·ekN1)^T + (w2·ekb1 + w2b)
    k_gemm<2, 0><<<gNe, 256>>>(t, M2s, DIM, neigh, M2n, DIM,
                               nullptr, nullptr, 0, b2, hiI, n_e);
    // src_com = [h_iI | e_emb] @ w1^T + w1b
    k_gemm<2, 0><<<gNe, 256>>>(hiI, w1W, 2 * DIM, e_emb, w1W + DIM, 2 * DIM,
                               nullptr, nullptr, 0, w1b, srcc, n_e);

    // ---- collab graph: CSR build + edge-weighted gather-mean of src_com ----
    k_zero_i<<<(n_e + 255) / 256, 256>>>(cnt, n_e);
    k_hist<<<(Ec + 255) / 256, 256>>>(c_dst, cnt, Ec);
    k_scan1<<<nchunks, 256>>>(cnt, rowstart, chunkoff + 128, n_e);
    k_scan2<<<1, 256>>>(chunkoff + 128, chunkoff, nchunks);
    k_scan3<<<(n_e + 255) / 256, 256>>>(rowstart, cursor, chunkoff, n_e);
    k_scatter<true><<<(Ec + 255) / 256, 256>>>(c_src, c_dst, cf_ew, cursor, esrc, eew, Ec);
    k_agg_csr<true><<<gRows, 256>>>(srcc, rowstart, cnt, esrc, eew, neigh, n_e);

    // t1 = relu(e_emb @ eeS0^T + neigh @ eeN0^T + eeb0)
    k_gemm<2, 1><<<gNe, 256>>>(e_emb, eeS, DIM, neigh, eeN, DIM,
                               nullptr, nullptr, 0, eeb, t, n_e);
    // out = leaky( h_iI @ Ca^T + t1 @ F1^T + neigh @ F2^T + bf )
    k_gemm<3, 2><<<gNe, 256>>>(hiI, cW, 2 * DIM, t, F1, DIM, neigh, F2, DIM,
                               bfv, out, n_e);
}